// round 6
// baseline (speedup 1.0000x reference)
#include <cuda_runtime.h>
#include <cuda_fp16.h>
#include <cstdint>

// VectorQuantStraightThrough via warp-level HMMA (mma.sync m16n8k16 fp16),
// fp32-emulated dot with fp16 2-way splits, 3 cross terms.
//   z scaled by 2^3, e scaled by 2^15  =>  accum = 2^18 * dot  (exact scales)
//   2*dot = accum * 2^-17 (exact).  d2 = fl( fl(z2 - 2dot) + e2 ).
// Round 6: per-term accumulator chains (6 independent HMMA chains / warp)
// + coalesced prep kernel. z2/e2 orders identical to passing round-5 kernel.

#define NROWS (32 * 4096)   // 131072
#define DDIM  64
#define KCB   512
#define MT    128           // rows per CTA
#define NTILES (NROWS / MT) // 1024 CTAs
#define TPB   256

// smem byte offsets (rows padded to 72 halves = 144 B)
#define SM_B0   0           // e-split0 [512][72] half
#define SM_B1   73728       // e-split1
#define SM_A0   147456      // z-split0 [128][72] half
#define SM_A1   165888      // z-split1
#define SM_Z32  184320      // z tile fp32 [128][64]
#define SM_E2   217088      // e2 [512] float
#define SM_Z2   219136      // z2 [128] float
#define SM_VAL0 219648      // best val half0 [128] float
#define SM_VAL1 220160
#define SM_IDX0 220672      // best idx [128] int
#define SM_IDX1 221184
#define SM_TOTAL 221696

#define TWO_DOT_SCALE (1.0f / 131072.0f)   // 2^-17

// ---- device scratch ----
__device__ __half g_b0[KCB * DDIM];
__device__ __half g_b1[KCB * DDIM];
__device__ float  g_e2[KCB];

__device__ __forceinline__ void mma16816(float* c, const uint32_t* a,
                                         const uint32_t* b) {
    asm volatile(
        "mma.sync.aligned.m16n8k16.row.col.f32.f16.f16.f32 "
        "{%0,%1,%2,%3}, {%4,%5,%6,%7}, {%8,%9}, {%0,%1,%2,%3};"
        : "+f"(c[0]), "+f"(c[1]), "+f"(c[2]), "+f"(c[3])
        : "r"(a[0]), "r"(a[1]), "r"(a[2]), "r"(a[3]), "r"(b[0]), "r"(b[1]));
}

// ---------------- prep: e-splits (scaled 2^15) + ||e||^2 ------------------
// 4 CTAs x 128 threads; each CTA stages 128 codes into smem coalesced,
// then one code per thread (identical sequential chains to round 5).
__global__ __launch_bounds__(128, 1)
void vq_prep_kernel(const float* __restrict__ emb) {
    __shared__ float se[128 * DDIM];   // 32 KB
    const int tid = threadIdx.x;
    const int k0  = blockIdx.x * 128;

    const float4* src = (const float4*)(emb + (size_t)k0 * DDIM);
    float4* dst = (float4*)se;
    #pragma unroll
    for (int i = tid; i < 128 * DDIM / 4; i += 128) dst[i] = src[i];
    __syncthreads();

    const int k = k0 + tid;
    const float* e = se + tid * DDIM;
    float s = 0.f;
    #pragma unroll 8
    for (int d = 0; d < DDIM; d++) {
        const float v = e[d];
        s = fmaf(v, v, s);                     // exact round-2/5 e2 chain order
        const float sv = v * 32768.0f;         // exact
        const __half h0 = __float2half_rn(sv);
        const float  r  = sv - __half2float(h0);
        const __half h1 = __float2half_rn(r);
        g_b0[k * DDIM + d] = h0;
        g_b1[k * DDIM + d] = h1;
    }
    g_e2[k] = s;
}

// ---------------- main kernel ---------------------------------------------
__global__ __launch_bounds__(TPB, 1)
void vq_main_kernel(const float* __restrict__ z,
                    const float* __restrict__ emb,
                    float* __restrict__ out,
                    long long out_size) {
    extern __shared__ char smem[];
    const int tid = threadIdx.x;
    const int w   = tid >> 5;
    const int l   = tid & 31;
    const int tile = blockIdx.x;

    // ---- stage z tile fp32 (coalesced) ----
    {
        const float4* src = (const float4*)(z + (size_t)tile * MT * DDIM);
        float4* dst = (float4*)(smem + SM_Z32);
        #pragma unroll
        for (int i = tid; i < MT * DDIM / 4; i += TPB) dst[i] = src[i];
    }
    // ---- stage e-splits into padded smem (16B chunks) ----
    {
        const uint4* s0 = (const uint4*)g_b0;
        const uint4* s1 = (const uint4*)g_b1;
        #pragma unroll
        for (int c = tid; c < KCB * DDIM / 8; c += TPB) {   // 4096 chunks
            const int row = c >> 3, cc = c & 7;
            *(uint4*)(smem + SM_B0 + row * 144 + cc * 16) = s0[c];
            *(uint4*)(smem + SM_B1 + row * 144 + cc * 16) = s1[c];
        }
    }
    // e2
    #pragma unroll
    for (int i = tid; i < KCB; i += TPB)
        ((float*)(smem + SM_E2))[i] = g_e2[i];
    __syncthreads();

    // ---- convert z tile to fp16 splits (scaled 2^3), padded layout ----
    {
        const float* z32 = (const float*)(smem + SM_Z32);
        #pragma unroll
        for (int e = tid; e < MT * DDIM; e += TPB) {
            const int row = e >> 6, kk = e & 63;
            const float sv = z32[e] * 8.0f;    // exact
            const __half h0 = __float2half_rn(sv);
            const float  r  = sv - __half2float(h0);
            const __half h1 = __float2half_rn(r);
            *(__half*)(smem + SM_A0 + row * 144 + kk * 2) = h0;
            *(__half*)(smem + SM_A1 + row * 144 + kk * 2) = h1;
        }
    }
    // ---- z2 per row: EXACT round-2/5 evaluation order ----
    if (tid < MT) {
        const float* zr = (const float*)(smem + SM_Z32) + tid * DDIM;
        float c[8];
        #pragma unroll
        for (int p = 0; p < 8; p++) {
            float s = 0.f;
            #pragma unroll
            for (int j = 0; j < 8; j++) s = fmaf(zr[p + 8 * j], zr[p + 8 * j], s);
            c[p] = s;
        }
        const float lo = __fadd_rn(__fadd_rn(c[0], c[2]), __fadd_rn(c[4], c[6]));
        const float hi = __fadd_rn(__fadd_rn(c[1], c[3]), __fadd_rn(c[5], c[7]));
        ((float*)(smem + SM_Z2))[tid] = __fadd_rn(lo, hi);
    }
    __syncthreads();

    // ---- warp partition: 4 M-slices x 2 N-halves ----
    const int mrow0 = (w & 3) * 32;        // 32 rows per warp (2 m16 frags)
    const int nhalf = w >> 2;              // 0 or 1
    const int ncol0 = nhalf * 256;         // 32 n-tiles per warp
    const int lr = l >> 2;                 // 0..7
    const int kb = (l & 3) * 2;            // 0,2,4,6

    // ---- load A fragments (held in regs): [msub][split][ktile][4] ----
    uint32_t Af[2][2][4][4];
    #pragma unroll
    for (int m = 0; m < 2; m++) {
        const int r0 = mrow0 + m * 16 + lr;
        #pragma unroll
        for (int s = 0; s < 2; s++) {
            const char* Ab = smem + (s ? SM_A1 : SM_A0);
            #pragma unroll
            for (int kt = 0; kt < 4; kt++) {
                const int k0 = kt * 16 + kb;
                Af[m][s][kt][0] = *(const uint32_t*)(Ab + r0 * 144 + k0 * 2);
                Af[m][s][kt][1] = *(const uint32_t*)(Ab + (r0 + 8) * 144 + k0 * 2);
                Af[m][s][kt][2] = *(const uint32_t*)(Ab + r0 * 144 + (k0 + 8) * 2);
                Af[m][s][kt][3] = *(const uint32_t*)(Ab + (r0 + 8) * 144 + (k0 + 8) * 2);
            }
        }
    }

    const float* z2s = (const float*)(smem + SM_Z2);
    const float* e2s = (const float*)(smem + SM_E2);
    float z2v[2][2];
    #pragma unroll
    for (int m = 0; m < 2; m++) {
        z2v[m][0] = z2s[mrow0 + m * 16 + lr];
        z2v[m][1] = z2s[mrow0 + m * 16 + lr + 8];
    }

    float bv[2][2] = {{3.4e38f, 3.4e38f}, {3.4e38f, 3.4e38f}};
    int   bi[2][2] = {{0, 0}, {0, 0}};

    // ---- main loop: 32 n-tiles, 6 independent accumulator chains ----
    for (int j = 0; j < 32; j++) {
        const int col0 = ncol0 + j * 8;
        const int nr = col0 + lr;

        uint32_t Bf[2][4][2];
        #pragma unroll
        for (int s = 0; s < 2; s++) {
            const char* Bb = smem + (s ? SM_B1 : SM_B0);
            #pragma unroll
            for (int kt = 0; kt < 4; kt++) {
                const int k0 = kt * 16 + kb;
                Bf[s][kt][0] = *(const uint32_t*)(Bb + nr * 144 + k0 * 2);
                Bf[s][kt][1] = *(const uint32_t*)(Bb + nr * 144 + (k0 + 8) * 2);
            }
        }

        // three per-term accumulators x two m-frags = 6 chains, depth 4
        float C01[2][4] = {{0.f,0.f,0.f,0.f},{0.f,0.f,0.f,0.f}};  // a0*b1
        float C10[2][4] = {{0.f,0.f,0.f,0.f},{0.f,0.f,0.f,0.f}};  // a1*b0
        float C00[2][4] = {{0.f,0.f,0.f,0.f},{0.f,0.f,0.f,0.f}};  // a0*b0
        #pragma unroll
        for (int kt = 0; kt < 4; kt++) {
            mma16816(C01[0], Af[0][0][kt], Bf[1][kt]);
            mma16816(C01[1], Af[1][0][kt], Bf[1][kt]);
            mma16816(C10[0], Af[0][1][kt], Bf[0][kt]);
            mma16816(C10[1], Af[1][1][kt], Bf[0][kt]);
            mma16816(C00[0], Af[0][0][kt], Bf[0][kt]);
            mma16816(C00[1], Af[1][0][kt], Bf[0][kt]);
        }

        // epilogue: combine small-first, reference rounding, running argmin
        const int ca = col0 + kb;
        const float e2a = e2s[ca], e2b = e2s[ca + 1];
        #pragma unroll
        for (int m = 0; m < 2; m++) {
            float td[4];
            #pragma unroll
            for (int q = 0; q < 4; q++) {
                const float s = __fadd_rn(__fadd_rn(C01[m][q], C10[m][q]),
                                          C00[m][q]);
                td[q] = __fmul_rn(s, TWO_DOT_SCALE);   // exact scale
            }
            const float d00 = __fadd_rn(__fsub_rn(z2v[m][0], td[0]), e2a);
            const float d01 = __fadd_rn(__fsub_rn(z2v[m][0], td[1]), e2b);
            const float d10 = __fadd_rn(__fsub_rn(z2v[m][1], td[2]), e2a);
            const float d11 = __fadd_rn(__fsub_rn(z2v[m][1], td[3]), e2b);
            if (d00 < bv[m][0]) { bv[m][0] = d00; bi[m][0] = ca; }
            if (d01 < bv[m][0]) { bv[m][0] = d01; bi[m][0] = ca + 1; }
            if (d10 < bv[m][1]) { bv[m][1] = d10; bi[m][1] = ca; }
            if (d11 < bv[m][1]) { bv[m][1] = d11; bi[m][1] = ca + 1; }
        }
    }

    // ---- reduce across the 4 lanes of each quad (min, lowest index on tie)
    #pragma unroll
    for (int m = 0; m < 2; m++) {
        #pragma unroll
        for (int h = 0; h < 2; h++) {
            float v = bv[m][h];
            int   i = bi[m][h];
            #pragma unroll
            for (int s = 1; s <= 2; s <<= 1) {
                const float ov = __shfl_xor_sync(0xFFFFFFFFu, v, s);
                const int   oi = __shfl_xor_sync(0xFFFFFFFFu, i, s);
                if (ov < v || (ov == v && oi < i)) { v = ov; i = oi; }
            }
            if ((l & 3) == 0) {
                const int row = mrow0 + m * 16 + lr + h * 8;
                ((float*)(smem + (nhalf ? SM_VAL1 : SM_VAL0)))[row] = v;
                ((int*)  (smem + (nhalf ? SM_IDX1 : SM_IDX0)))[row] = i;
            }
        }
    }
    __syncthreads();

    // ---- output stage: merge halves, gather emb fp32, write ----
    const float* v0s = (const float*)(smem + SM_VAL0);
    const float* v1s = (const float*)(smem + SM_VAL1);
    const int*   i0s = (const int*)(smem + SM_IDX0);
    const int*   i1s = (const int*)(smem + SM_IDX1);

    const int r  = tid >> 1;            // local row 0..127
    const int hh = tid & 1;             // half of the 64 dims
    const int idx = (v1s[r] < v0s[r]) ? i1s[r] : i0s[r];  // half0 wins ties

    const long long n   = (long long)tile * MT + r;
    const long long ND  = (long long)NROWS * DDIM;   // 8388608
    const float4* ev = (const float4*)(emb + (long long)idx * DDIM) + hh * 8;
    const long long off = n * DDIM + hh * 32;

    if (out_size >= ND) {
        float4* o = (float4*)(out + off);
        #pragma unroll
        for (int q = 0; q < 8; q++) o[q] = ev[q];
    }
    if (out_size >= 2 * ND) {
        float4* o = (float4*)(out + ND + off);
        #pragma unroll
        for (int q = 0; q < 8; q++) o[q] = ev[q];
    }
    if (hh == 0) {   // indices as float (0..511 exact)
        if (out_size >= 2 * ND + NROWS)      out[2 * ND + n] = (float)idx;
        else if (out_size == ND + NROWS)     out[ND + n]     = (float)idx;
        else if (out_size == NROWS)          out[n]          = (float)idx;
    }
}

// ---------------------------------------------------------------------------
extern "C" void kernel_launch(void* const* d_in, const int* in_sizes, int n_in,
                              void* d_out, int out_size) {
    const float* z   = (const float*)d_in[0];
    const float* emb = (const float*)d_in[1];
    if (n_in >= 2 && in_sizes[0] == KCB * DDIM && in_sizes[1] == NROWS * DDIM) {
        z   = (const float*)d_in[1];
        emb = (const float*)d_in[0];
    }

    static int configured = -1;
    if (configured < 0) {
        cudaFuncSetAttribute(vq_main_kernel,
                             cudaFuncAttributeMaxDynamicSharedMemorySize, SM_TOTAL);
        configured = 1;
    }

    vq_prep_kernel<<<4, 128>>>(emb);
    vq_main_kernel<<<NTILES, TPB, SM_TOTAL>>>(z, emb, (float*)d_out,
                                              (long long)out_size);
}